// round 12
// baseline (speedup 1.0000x reference)
#include <cuda_runtime.h>
#include <math.h>

// Problem constants (fixed by the dataset)
#define NN   100000
#define DIMX 256
#define HIDN 16
#define NCLS 64
#define NEG  0.2f

// ---------------------------------------------------------------------------
// Static device scratch (no allocation allowed). ~27 MB total.
// float4 arrays guarantee 16B alignment for vector-atomic targets.
// ---------------------------------------------------------------------------
__device__ float4 g_h1  [NN * 4];   // layer1 pre-aggregation h = x@W1   [N,16]
__device__ float4 g_h1b [NN * 4];   // layer1 output (post relu)         [N,16]
__device__ float4 g_agg1[NN * 4];   // layer1 unnormalized aggregation   [N,16]
__device__ float4 g_agg2[NN * 4];   // layer2 unnormalized aggregation (16-dim space)
__device__ float  g_as1[NN], g_ad1[NN];   // layer1 alpha_src / alpha_dst per node
__device__ float  g_as2[NN], g_ad2[NN];   // layer2 alpha_src / alpha_dst per node
__device__ float  g_den1[NN], g_den2[NN]; // softmax denominators
__device__ float  g_was2[HIDN], g_wad2[HIDN]; // W2 @ a_src2, W2 @ a_dst2

__device__ __forceinline__ float lrelu(float x) {
    return fmaxf(x, 0.f) + NEG * fminf(x, 0.f);
}

// ---------------------------------------------------------------------------
// K0: precompute w_as2 = W2 @ a_src2, w_ad2 = W2 @ a_dst2 (16-vectors)
// ---------------------------------------------------------------------------
__global__ void prep_w2_kernel(const float* __restrict__ W2,
                               const float* __restrict__ a_s2,
                               const float* __restrict__ a_d2) {
    int t = threadIdx.x;
    if (t < 16) {
        float s = 0.f;
        #pragma unroll
        for (int j = 0; j < NCLS; j++) s += W2[t * NCLS + j] * a_s2[j];
        g_was2[t] = s;
    } else if (t < 32) {
        int r = t - 16;
        float s = 0.f;
        #pragma unroll
        for (int j = 0; j < NCLS; j++) s += W2[r * NCLS + j] * a_d2[j];
        g_wad2[r] = s;
    }
}

// ---------------------------------------------------------------------------
// K1: h1 = x @ W1 ; alpha_s1/alpha_d1 ; self-loop init of denom1/agg1.
// Block = 256 threads = 16 nodes x 16 output-cols. x tile + transposed/padded
// W1 in smem; all LDS accesses conflict-free (W row pad 260 floats).
// ---------------------------------------------------------------------------
__global__ void __launch_bounds__(256) gemm1_kernel(const float4* __restrict__ x4,
                                                    const float*  __restrict__ W1,
                                                    const float*  __restrict__ a_s1,
                                                    const float*  __restrict__ a_d1) {
    __shared__ float4 xs[16 * 64];                 // 16 nodes x 256 floats
    __shared__ __align__(16) float wt[16 * 260];   // wt[j*260 + k] = W1[k*16+j], padded

    const int tid = threadIdx.x;
    const int nb  = blockIdx.x * 16;

    // load W1 transposed (coalesced read, scattered smem write, once per block)
    for (int idx = tid; idx < DIMX * HIDN; idx += 256) {
        int j = idx & 15, k = idx >> 4;
        wt[j * 260 + k] = W1[idx];
    }
    // load x tile: 16 nodes x 64 float4, coalesced
    for (int idx = tid; idx < 16 * 64; idx += 256)
        xs[idx] = x4[(size_t)nb * 64 + idx];
    __syncthreads();

    const int n = tid >> 4;          // node within tile (warp = 2 nodes)
    const int j = tid & 15;          // output column
    const float4* wrow = (const float4*)wt + j * 65;
    const float4* xrow = xs + n * 64;

    float acc = 0.f;
    #pragma unroll 8
    for (int k = 0; k < 64; k++) {
        float4 xv = xrow[k];
        float4 wv = wrow[k];
        acc += xv.x * wv.x; acc += xv.y * wv.y;
        acc += xv.z * wv.z; acc += xv.w * wv.w;
    }

    const int i = nb + n;
    ((float*)g_h1)[(size_t)i * 16 + j] = acc;

    // alpha_s / alpha_d: 16-lane butterfly reductions (stay within half-warp)
    float vs = acc * __ldg(a_s1 + j);
    vs += __shfl_xor_sync(0xffffffffu, vs, 1);
    vs += __shfl_xor_sync(0xffffffffu, vs, 2);
    vs += __shfl_xor_sync(0xffffffffu, vs, 4);
    vs += __shfl_xor_sync(0xffffffffu, vs, 8);
    float vd = acc * __ldg(a_d1 + j);
    vd += __shfl_xor_sync(0xffffffffu, vd, 1);
    vd += __shfl_xor_sync(0xffffffffu, vd, 2);
    vd += __shfl_xor_sync(0xffffffffu, vd, 4);
    vd += __shfl_xor_sync(0xffffffffu, vd, 8);

    // self-loop (i,i): initialize denom and aggregation (no atomics needed)
    float ee = __expf(lrelu(vs + vd));
    if (j == 0) { g_as1[i] = vs; g_ad1[i] = vd; g_den1[i] = ee; }
    ((float*)g_agg1)[(size_t)i * 16 + j] = ee * acc;
}

// ---------------------------------------------------------------------------
// K2/K4: single fused edge pass per layer. edge_index is INT32 (jax default
// x64-disabled downcasts int64->int32; harness dtype table has no int64).
// Each thread handles 4 edges: one int4 load of src, one of dst (coalesced),
// then per edge: ee = exp(lrelu(as+ad)), denom[dst] += ee (scalar RED),
// agg[dst] += ee*h16[src] (4x 16B vector RED via atomicAdd(float4*)).
// 8 independent gathers in flight per thread hide L2/DRAM latency.
// ---------------------------------------------------------------------------
__global__ void __launch_bounds__(256) edge_kernel(const int* __restrict__ ei,
                                                   int E, int layer) {
    const float*  as  = layer ? g_as2 : g_as1;
    const float*  ad  = layer ? g_ad2 : g_ad1;
    const float4* h4  = layer ? g_h1b : g_h1;
    float*        den = layer ? g_den2 : g_den1;
    float4*       agg = layer ? g_agg2 : g_agg1;

    int e4 = blockIdx.x * 256 + threadIdx.x;   // group of 4 edges
    int e0 = e4 * 4;
    if (e0 + 3 < E) {
        int4 sv = __ldg((const int4*)(ei) + e4);
        int4 dv = __ldg((const int4*)(ei + E) + e4);
        int s[4] = {sv.x, sv.y, sv.z, sv.w};
        int d[4] = {dv.x, dv.y, dv.z, dv.w};

        float ts[4], td[4];
        #pragma unroll
        for (int k = 0; k < 4; k++) ts[k] = __ldg(as + s[k]);
        #pragma unroll
        for (int k = 0; k < 4; k++) td[k] = __ldg(ad + d[k]);

        #pragma unroll
        for (int k = 0; k < 4; k++) {
            float ee = __expf(lrelu(ts[k] + td[k]));
            atomicAdd(den + d[k], ee);
            #pragma unroll
            for (int q = 0; q < 4; q++) {
                float4 hv = __ldg(h4 + (size_t)s[k] * 4 + q);
                float4 v  = make_float4(ee * hv.x, ee * hv.y, ee * hv.z, ee * hv.w);
                atomicAdd(agg + (size_t)d[k] * 4 + q, v);
            }
        }
    } else {
        for (int e = e0; e < E; e++) {
            int s = __ldg(ei + e);
            int d = __ldg(ei + E + e);
            float ee = __expf(lrelu(__ldg(as + s) + __ldg(ad + d)));
            atomicAdd(den + d, ee);
            #pragma unroll
            for (int q = 0; q < 4; q++) {
                float4 hv = __ldg(h4 + (size_t)s * 4 + q);
                float4 v  = make_float4(ee * hv.x, ee * hv.y, ee * hv.z, ee * hv.w);
                atomicAdd(agg + (size_t)d * 4 + q, v);
            }
        }
    }
}

// ---------------------------------------------------------------------------
// K3: finalize layer1 (normalize, +b1, relu) and prep layer2
// (alpha_s2/alpha_d2 via precomputed w_as2/w_ad2; self-loop init den2/agg2).
// ---------------------------------------------------------------------------
__global__ void __launch_bounds__(256) mid_kernel(const float* __restrict__ b1) {
    const int tid = threadIdx.x;
    const int nb  = blockIdx.x * 16;
    const int n = tid >> 4, j = tid & 15;
    const int i = nb + n;

    float rd = 1.0f / g_den1[i];
    float h  = fmaf(((const float*)g_agg1)[(size_t)i * 16 + j], rd, __ldg(b1 + j));
    h = fmaxf(h, 0.f);
    ((float*)g_h1b)[(size_t)i * 16 + j] = h;

    float vs = h * g_was2[j];
    vs += __shfl_xor_sync(0xffffffffu, vs, 1);
    vs += __shfl_xor_sync(0xffffffffu, vs, 2);
    vs += __shfl_xor_sync(0xffffffffu, vs, 4);
    vs += __shfl_xor_sync(0xffffffffu, vs, 8);
    float vd = h * g_wad2[j];
    vd += __shfl_xor_sync(0xffffffffu, vd, 1);
    vd += __shfl_xor_sync(0xffffffffu, vd, 2);
    vd += __shfl_xor_sync(0xffffffffu, vd, 4);
    vd += __shfl_xor_sync(0xffffffffu, vd, 8);

    float ee = __expf(lrelu(vs + vd));
    if (j == 0) { g_as2[i] = vs; g_ad2[i] = vd; g_den2[i] = ee; }
    ((float*)g_agg2)[(size_t)i * 16 + j] = ee * h;
}

// ---------------------------------------------------------------------------
// K5: out = log_softmax( (agg2/den2) @ W2 + b2 ). One warp per node, each
// lane owns 2 of the 64 classes. W2/b2 staged in smem (conflict-free reads).
// ---------------------------------------------------------------------------
__global__ void __launch_bounds__(256) final_kernel(const float* __restrict__ W2,
                                                    const float* __restrict__ b2,
                                                    float* __restrict__ out) {
    __shared__ float ws[HIDN * NCLS];
    __shared__ float bs[NCLS];
    const int tid = threadIdx.x;
    for (int idx = tid; idx < HIDN * NCLS; idx += 256) ws[idx] = W2[idx];
    if (tid < NCLS) bs[tid] = b2[tid];
    __syncthreads();

    const int w    = tid >> 5;
    const int lane = tid & 31;
    const int i    = blockIdx.x * 8 + w;

    float rd = 1.0f / g_den2[i];
    const float4* a4 = g_agg2 + (size_t)i * 4;
    float v[16];
    #pragma unroll
    for (int q = 0; q < 4; q++) {
        float4 t = __ldg(a4 + q);   // warp-uniform address -> broadcast
        v[4 * q + 0] = t.x; v[4 * q + 1] = t.y;
        v[4 * q + 2] = t.z; v[4 * q + 3] = t.w;
    }

    float s0 = 0.f, s1 = 0.f;
    #pragma unroll
    for (int k = 0; k < 16; k++) {
        s0 = fmaf(v[k], ws[k * NCLS + lane],      s0);
        s1 = fmaf(v[k], ws[k * NCLS + 32 + lane], s1);
    }
    float o0 = fmaf(rd, s0, bs[lane]);
    float o1 = fmaf(rd, s1, bs[lane + 32]);

    float m = fmaxf(o0, o1);
    #pragma unroll
    for (int d = 1; d < 32; d <<= 1)
        m = fmaxf(m, __shfl_xor_sync(0xffffffffu, m, d));
    float se = __expf(o0 - m) + __expf(o1 - m);
    #pragma unroll
    for (int d = 1; d < 32; d <<= 1)
        se += __shfl_xor_sync(0xffffffffu, se, d);
    float lse = m + __logf(se);

    out[(size_t)i * 64 + lane]      = o0 - lse;
    out[(size_t)i * 64 + 32 + lane] = o1 - lse;
}

// ---------------------------------------------------------------------------
// kernel_launch: inputs in metadata order:
// x, edge_index(int32 [2,E]), W1, a_src1, a_dst1, b1, W2, a_src2, a_dst2, b2
// ---------------------------------------------------------------------------
extern "C" void kernel_launch(void* const* d_in, const int* in_sizes, int n_in,
                              void* d_out, int out_size) {
    const float* x   = (const float*)d_in[0];
    const int*   ei  = (const int*)d_in[1];     // int32! (jax x64 disabled)
    const float* W1  = (const float*)d_in[2];
    const float* as1 = (const float*)d_in[3];
    const float* ad1 = (const float*)d_in[4];
    const float* b1  = (const float*)d_in[5];
    const float* W2  = (const float*)d_in[6];
    const float* as2 = (const float*)d_in[7];
    const float* ad2 = (const float*)d_in[8];
    const float* b2  = (const float*)d_in[9];
    const int E = in_sizes[1] / 2;
    const int egroups = (E + 3) / 4;

    prep_w2_kernel<<<1, 32>>>(W2, as2, ad2);
    gemm1_kernel<<<NN / 16, 256>>>((const float4*)x, W1, as1, ad1);
    edge_kernel<<<(egroups + 255) / 256, 256>>>(ei, E, 0);
    mid_kernel<<<NN / 16, 256>>>(b1);
    edge_kernel<<<(egroups + 255) / 256, 256>>>(ei, E, 1);
    final_kernel<<<NN / 8, 256>>>(W2, b2, (float*)d_out);
}

// round 13
// speedup vs baseline: 1.0012x; 1.0012x over previous
#include <cuda_runtime.h>
#include <math.h>

// Problem constants (fixed by the dataset)
#define NN   100000
#define DIMX 256
#define HIDN 16
#define NCLS 64
#define NEG  0.2f

// ---------------------------------------------------------------------------
// Static device scratch (no allocation allowed). ~27 MB total.
// float4 arrays guarantee 16B alignment for vector-atomic targets.
// ---------------------------------------------------------------------------
__device__ float4 g_h1  [NN * 4];   // layer1 pre-aggregation h = x@W1   [N,16]
__device__ float4 g_h1b [NN * 4];   // layer1 output (post relu)         [N,16]
__device__ float4 g_agg1[NN * 4];   // layer1 unnormalized aggregation   [N,16]
__device__ float4 g_agg2[NN * 4];   // layer2 unnormalized aggregation (16-dim space)
__device__ float  g_as1[NN], g_ad1[NN];   // layer1 alpha_src / alpha_dst per node
__device__ float  g_as2[NN], g_ad2[NN];   // layer2 alpha_src / alpha_dst per node
__device__ float  g_den1[NN], g_den2[NN]; // softmax denominators
__device__ float  g_was2[HIDN], g_wad2[HIDN]; // W2 @ a_src2, W2 @ a_dst2

__device__ __forceinline__ float lrelu(float x) {
    return fmaxf(x, 0.f) + NEG * fminf(x, 0.f);
}

// ---------------------------------------------------------------------------
// K0: precompute w_as2 = W2 @ a_src2, w_ad2 = W2 @ a_dst2 (16-vectors)
// ---------------------------------------------------------------------------
__global__ void prep_w2_kernel(const float* __restrict__ W2,
                               const float* __restrict__ a_s2,
                               const float* __restrict__ a_d2) {
    int t = threadIdx.x;
    if (t < 16) {
        float s = 0.f;
        #pragma unroll
        for (int j = 0; j < NCLS; j++) s += W2[t * NCLS + j] * a_s2[j];
        g_was2[t] = s;
    } else if (t < 32) {
        int r = t - 16;
        float s = 0.f;
        #pragma unroll
        for (int j = 0; j < NCLS; j++) s += W2[r * NCLS + j] * a_d2[j];
        g_wad2[r] = s;
    }
}

// ---------------------------------------------------------------------------
// K1: h1 = x @ W1 ; alpha_s1/alpha_d1 ; self-loop init of denom1/agg1.
// Block = 256 threads = 16 nodes x 16 output-cols. x tile + transposed/padded
// W1 in smem; all LDS accesses conflict-free (W row pad 260 floats).
// ---------------------------------------------------------------------------
__global__ void __launch_bounds__(256) gemm1_kernel(const float4* __restrict__ x4,
                                                    const float*  __restrict__ W1,
                                                    const float*  __restrict__ a_s1,
                                                    const float*  __restrict__ a_d1) {
    __shared__ float4 xs[16 * 64];                 // 16 nodes x 256 floats
    __shared__ __align__(16) float wt[16 * 260];   // wt[j*260 + k] = W1[k*16+j], padded

    const int tid = threadIdx.x;
    const int nb  = blockIdx.x * 16;

    // load W1 transposed (coalesced read, scattered smem write, once per block)
    for (int idx = tid; idx < DIMX * HIDN; idx += 256) {
        int j = idx & 15, k = idx >> 4;
        wt[j * 260 + k] = W1[idx];
    }
    // load x tile: 16 nodes x 64 float4, coalesced
    for (int idx = tid; idx < 16 * 64; idx += 256)
        xs[idx] = x4[(size_t)nb * 64 + idx];
    __syncthreads();

    const int n = tid >> 4;          // node within tile (warp = 2 nodes)
    const int j = tid & 15;          // output column
    const float4* wrow = (const float4*)wt + j * 65;
    const float4* xrow = xs + n * 64;

    float acc = 0.f;
    #pragma unroll 8
    for (int k = 0; k < 64; k++) {
        float4 xv = xrow[k];
        float4 wv = wrow[k];
        acc += xv.x * wv.x; acc += xv.y * wv.y;
        acc += xv.z * wv.z; acc += xv.w * wv.w;
    }

    const int i = nb + n;
    ((float*)g_h1)[(size_t)i * 16 + j] = acc;

    // alpha_s / alpha_d: 16-lane butterfly reductions (stay within half-warp)
    float vs = acc * __ldg(a_s1 + j);
    vs += __shfl_xor_sync(0xffffffffu, vs, 1);
    vs += __shfl_xor_sync(0xffffffffu, vs, 2);
    vs += __shfl_xor_sync(0xffffffffu, vs, 4);
    vs += __shfl_xor_sync(0xffffffffu, vs, 8);
    float vd = acc * __ldg(a_d1 + j);
    vd += __shfl_xor_sync(0xffffffffu, vd, 1);
    vd += __shfl_xor_sync(0xffffffffu, vd, 2);
    vd += __shfl_xor_sync(0xffffffffu, vd, 4);
    vd += __shfl_xor_sync(0xffffffffu, vd, 8);

    // self-loop (i,i): initialize denom and aggregation (no atomics needed)
    float ee = __expf(lrelu(vs + vd));
    if (j == 0) { g_as1[i] = vs; g_ad1[i] = vd; g_den1[i] = ee; }
    ((float*)g_agg1)[(size_t)i * 16 + j] = ee * acc;
}

// ---------------------------------------------------------------------------
// K2/K4: single fused edge pass per layer. edge_index is INT32 (jax default
// x64-disabled downcasts int64->int32; harness dtype table has no int64).
// Each thread handles 4 edges: one int4 load of src, one of dst (coalesced),
// then per edge: ee = exp(lrelu(as+ad)), denom[dst] += ee (scalar RED),
// agg[dst] += ee*h16[src] (4x 16B vector RED via atomicAdd(float4*)).
// 8 independent gathers in flight per thread hide L2/DRAM latency.
// ---------------------------------------------------------------------------
__global__ void __launch_bounds__(256) edge_kernel(const int* __restrict__ ei,
                                                   int E, int layer) {
    const float*  as  = layer ? g_as2 : g_as1;
    const float*  ad  = layer ? g_ad2 : g_ad1;
    const float4* h4  = layer ? g_h1b : g_h1;
    float*        den = layer ? g_den2 : g_den1;
    float4*       agg = layer ? g_agg2 : g_agg1;

    int e4 = blockIdx.x * 256 + threadIdx.x;   // group of 4 edges
    int e0 = e4 * 4;
    if (e0 + 3 < E) {
        int4 sv = __ldg((const int4*)(ei) + e4);
        int4 dv = __ldg((const int4*)(ei + E) + e4);
        int s[4] = {sv.x, sv.y, sv.z, sv.w};
        int d[4] = {dv.x, dv.y, dv.z, dv.w};

        float ts[4], td[4];
        #pragma unroll
        for (int k = 0; k < 4; k++) ts[k] = __ldg(as + s[k]);
        #pragma unroll
        for (int k = 0; k < 4; k++) td[k] = __ldg(ad + d[k]);

        #pragma unroll
        for (int k = 0; k < 4; k++) {
            float ee = __expf(lrelu(ts[k] + td[k]));
            atomicAdd(den + d[k], ee);
            #pragma unroll
            for (int q = 0; q < 4; q++) {
                float4 hv = __ldg(h4 + (size_t)s[k] * 4 + q);
                float4 v  = make_float4(ee * hv.x, ee * hv.y, ee * hv.z, ee * hv.w);
                atomicAdd(agg + (size_t)d[k] * 4 + q, v);
            }
        }
    } else {
        for (int e = e0; e < E; e++) {
            int s = __ldg(ei + e);
            int d = __ldg(ei + E + e);
            float ee = __expf(lrelu(__ldg(as + s) + __ldg(ad + d)));
            atomicAdd(den + d, ee);
            #pragma unroll
            for (int q = 0; q < 4; q++) {
                float4 hv = __ldg(h4 + (size_t)s * 4 + q);
                float4 v  = make_float4(ee * hv.x, ee * hv.y, ee * hv.z, ee * hv.w);
                atomicAdd(agg + (size_t)d * 4 + q, v);
            }
        }
    }
}

// ---------------------------------------------------------------------------
// K3: finalize layer1 (normalize, +b1, relu) and prep layer2
// (alpha_s2/alpha_d2 via precomputed w_as2/w_ad2; self-loop init den2/agg2).
// ---------------------------------------------------------------------------
__global__ void __launch_bounds__(256) mid_kernel(const float* __restrict__ b1) {
    const int tid = threadIdx.x;
    const int nb  = blockIdx.x * 16;
    const int n = tid >> 4, j = tid & 15;
    const int i = nb + n;

    float rd = 1.0f / g_den1[i];
    float h  = fmaf(((const float*)g_agg1)[(size_t)i * 16 + j], rd, __ldg(b1 + j));
    h = fmaxf(h, 0.f);
    ((float*)g_h1b)[(size_t)i * 16 + j] = h;

    float vs = h * g_was2[j];
    vs += __shfl_xor_sync(0xffffffffu, vs, 1);
    vs += __shfl_xor_sync(0xffffffffu, vs, 2);
    vs += __shfl_xor_sync(0xffffffffu, vs, 4);
    vs += __shfl_xor_sync(0xffffffffu, vs, 8);
    float vd = h * g_wad2[j];
    vd += __shfl_xor_sync(0xffffffffu, vd, 1);
    vd += __shfl_xor_sync(0xffffffffu, vd, 2);
    vd += __shfl_xor_sync(0xffffffffu, vd, 4);
    vd += __shfl_xor_sync(0xffffffffu, vd, 8);

    float ee = __expf(lrelu(vs + vd));
    if (j == 0) { g_as2[i] = vs; g_ad2[i] = vd; g_den2[i] = ee; }
    ((float*)g_agg2)[(size_t)i * 16 + j] = ee * h;
}

// ---------------------------------------------------------------------------
// K5: out = log_softmax( (agg2/den2) @ W2 + b2 ). One warp per node, each
// lane owns 2 of the 64 classes. W2/b2 staged in smem (conflict-free reads).
// ---------------------------------------------------------------------------
__global__ void __launch_bounds__(256) final_kernel(const float* __restrict__ W2,
                                                    const float* __restrict__ b2,
                                                    float* __restrict__ out) {
    __shared__ float ws[HIDN * NCLS];
    __shared__ float bs[NCLS];
    const int tid = threadIdx.x;
    for (int idx = tid; idx < HIDN * NCLS; idx += 256) ws[idx] = W2[idx];
    if (tid < NCLS) bs[tid] = b2[tid];
    __syncthreads();

    const int w    = tid >> 5;
    const int lane = tid & 31;
    const int i    = blockIdx.x * 8 + w;

    float rd = 1.0f / g_den2[i];
    const float4* a4 = g_agg2 + (size_t)i * 4;
    float v[16];
    #pragma unroll
    for (int q = 0; q < 4; q++) {
        float4 t = __ldg(a4 + q);   // warp-uniform address -> broadcast
        v[4 * q + 0] = t.x; v[4 * q + 1] = t.y;
        v[4 * q + 2] = t.z; v[4 * q + 3] = t.w;
    }

    float s0 = 0.f, s1 = 0.f;
    #pragma unroll
    for (int k = 0; k < 16; k++) {
        s0 = fmaf(v[k], ws[k * NCLS + lane],      s0);
        s1 = fmaf(v[k], ws[k * NCLS + 32 + lane], s1);
    }
    float o0 = fmaf(rd, s0, bs[lane]);
    float o1 = fmaf(rd, s1, bs[lane + 32]);

    float m = fmaxf(o0, o1);
    #pragma unroll
    for (int d = 1; d < 32; d <<= 1)
        m = fmaxf(m, __shfl_xor_sync(0xffffffffu, m, d));
    float se = __expf(o0 - m) + __expf(o1 - m);
    #pragma unroll
    for (int d = 1; d < 32; d <<= 1)
        se += __shfl_xor_sync(0xffffffffu, se, d);
    float lse = m + __logf(se);

    out[(size_t)i * 64 + lane]      = o0 - lse;
    out[(size_t)i * 64 + 32 + lane] = o1 - lse;
}

// ---------------------------------------------------------------------------
// kernel_launch: inputs in metadata order:
// x, edge_index(int32 [2,E]), W1, a_src1, a_dst1, b1, W2, a_src2, a_dst2, b2
// ---------------------------------------------------------------------------
extern "C" void kernel_launch(void* const* d_in, const int* in_sizes, int n_in,
                              void* d_out, int out_size) {
    const float* x   = (const float*)d_in[0];
    const int*   ei  = (const int*)d_in[1];     // int32! (jax x64 disabled)
    const float* W1  = (const float*)d_in[2];
    const float* as1 = (const float*)d_in[3];
    const float* ad1 = (const float*)d_in[4];
    const float* b1  = (const float*)d_in[5];
    const float* W2  = (const float*)d_in[6];
    const float* as2 = (const float*)d_in[7];
    const float* ad2 = (const float*)d_in[8];
    const float* b2  = (const float*)d_in[9];
    const int E = in_sizes[1] / 2;
    const int egroups = (E + 3) / 4;

    prep_w2_kernel<<<1, 32>>>(W2, as2, ad2);
    gemm1_kernel<<<NN / 16, 256>>>((const float4*)x, W1, as1, ad1);
    edge_kernel<<<(egroups + 255) / 256, 256>>>(ei, E, 0);
    mid_kernel<<<NN / 16, 256>>>(b1);
    edge_kernel<<<(egroups + 255) / 256, 256>>>(ei, E, 1);
    final_kernel<<<NN / 8, 256>>>(W2, b2, (float*)d_out);
}